// round 15
// baseline (speedup 1.0000x reference)
#include <cuda_runtime.h>
#include <cstdint>
#include <cstddef>

// Problem dims
#define BB    64
#define TT    512
#define IDIM  512
#define HH    512
#define RING  8

// Tiling
#define TM    16
#define TN    32
#define NBAND (BB/TM)       // 4
#define NQ    (HH/TN)       // 16 (CTA-level releases)
#define NCTA  128
#define NTHR  256

#define AS_STRIDE 1028
#define RMS 32              // Red m-stride (floats)
#define RWS 512             // Red slice stride (floats)
#define NSLICE 16           // 8 warps x 2 folded k-subslices

// SMEM layout (floats): As | Wn (k-major) | Red
#define AS_OFF  0
#define WS_OFF  (TM*AS_STRIDE)                  // 16448
#define RED_OFF (WS_OFF + 1024*32)              // + 32768
#define SMEM_FLOATS (RED_OFF + NSLICE*RWS)      // + 8192 = 57408 (~229.6 KB)

__device__ float g_h1[RING][BB][HH];
__device__ int   g_done1[TT*NBAND];
__device__ int   g_done2[TT*NBAND];

__global__ void rnn_init_counters() {
    int i = blockIdx.x * blockDim.x + threadIdx.x;
    if (i < TT*NBAND) { g_done1[i] = 0; g_done2[i] = 0; }
}

__device__ __forceinline__ int ld_acq(const int* p) {
    int v;
    asm volatile("ld.acquire.gpu.global.u32 %0, [%1];" : "=r"(v) : "l"(p));
    return v;
}
__device__ __forceinline__ void red_release(int* p) {
    asm volatile("red.release.gpu.global.add.u32 [%0], %1;" :: "l"(p), "r"(1) : "memory");
}
__device__ __forceinline__ void spin_ge(const int* p, int target) {
    while (ld_acq(p) < target) { }
}
__device__ __forceinline__ void fma2(unsigned long long& acc,
                                     unsigned long long a, unsigned long long b) {
    asm("fma.rn.f32x2 %0, %1, %2, %0;" : "+l"(acc) : "l"(a), "l"(b));
}
__device__ __forceinline__ float4 ldcg4(const float* p) {
    return __ldcg((const float4*)p);
}

// tanh(x) = 1 - 2/(exp(2x)+1); ex2.approx + rcp.approx + 1 Newton (abs err ~1e-7)
__device__ __forceinline__ float fast_tanh(float v) {
    float e;
    asm("ex2.approx.f32 %0, %1;" : "=f"(e) : "f"(v * 2.8853900817779268f));
    float d = e + 1.0f;
    float r;
    asm("rcp.approx.f32 %0, %1;" : "=f"(r) : "f"(d));
    r = r * (2.0f - d * r);
    return 1.0f - 2.0f * r;
}

// Store one float4 (k = 4*kk..4*kk+3 of row mm) into swizzled row-major As.
// Swizzle: float idx = k ^ (8*(mm>>2)).
__device__ __forceinline__ void stage_f4(float* As, int mm, int kk, float4 v) {
    int idx = (kk*4) ^ ((mm >> 2) * 8);
    *(float4*)&As[mm*AS_STRIDE + idx] = v;
}

__global__ void __launch_bounds__(NTHR, 1) rnn_persistent(
    const float* __restrict__ x,    // [B,T,I]
    const float* __restrict__ h0,   // [L,B,H]
    const float* __restrict__ Wih,  // [L,H,I]
    const float* __restrict__ bih,  // [L,H]
    const float* __restrict__ Whh,  // [L,H,H]
    const float* __restrict__ bhh,  // [L,H]
    float* __restrict__ out)        // [B,T,H] then [L,B,H]
{
    extern __shared__ float smem[];
    float* As  = smem + AS_OFF;   // [16][1028] row-major, k-index XOR-swizzled
    float* Wn  = smem + WS_OFF;   // [1024 k][32 c] k-major
    float* Red = smem + RED_OFF;  // [16 slice][16 m x RMS]

    const int bx    = blockIdx.x;
    const int layer = bx >> 6;
    const int j     = bx & 63;
    const int r     = j >> 4;
    const int q     = j & 15;
    const int tid   = threadIdx.x;
    const int w     = tid >> 5;          // warp id; k range [128w, 128w+128)
    const int lane  = tid & 31;
    const bool on_path = (w >= 4);       // warps 4-7 own the recurrent K-half

    // GEMM lane mapping: lane = ks*8 + rg*4 + cgi
    const int ks   = lane >> 3;          // k-subslice 0..3 (interleaved at f32x2)
    const int rg   = (lane >> 2) & 1;    // rows 8rg .. 8rg+7
    const int cgi  = lane & 3;           // cols 8cgi .. 8cgi+7
    const int c0   = 8*cgi;
    const int xrA  = 16*rg;              // swizzle const, rows 8rg..8rg+3
    const int xrB  = 16*rg + 8;          // swizzle const, rows 8rg+4..8rg+7
    const int kf0  = 128*w + 2*ks;       // float-k base; iter i -> k = kf0 + 8i

    const float* Wi = Wih + (size_t)layer * HH * IDIM;
    const float* Wh = Whh + (size_t)layer * HH * HH;

    // one-time weight load into k-major Wn[k][c]; k<512 = Wih, k>=512 = Whh
    for (int it = tid; it < 32*128; it += NTHR) {
        int c  = it >> 7;         // 0..31
        int kk = it & 127;        // f4 index along k
        float4 vi = __ldg((const float4*)(Wi + (size_t)(q*TN + c)*IDIM) + kk);
        float4 vh = __ldg((const float4*)(Wh + (size_t)(q*TN + c)*HH)   + kk);
        Wn[(4*kk+0)*32 + c] = vi.x; Wn[(4*kk+1)*32 + c] = vi.y;
        Wn[(4*kk+2)*32 + c] = vi.z; Wn[(4*kk+3)*32 + c] = vi.w;
        Wn[(512+4*kk+0)*32 + c] = vh.x; Wn[(512+4*kk+1)*32 + c] = vh.y;
        Wn[(512+4*kk+2)*32 + c] = vh.z; Wn[(512+4*kk+3)*32 + c] = vh.w;
    }

    // per-warp staging constants: warp w owns As f4-columns [32w, 32w+32)
    const int c_st  = lane & 15;
    const int mr_st = lane >> 4;
    const int kk0   = 32*w + c_st;
    const int kk1   = kk0 + 16;
    const int s0    = on_path ? (kk0 - 128) : kk0;
    const int s1    = on_path ? (kk1 - 128) : kk1;

    // output mapping (reduce/store): 2 outputs per thread; Red addr = slice*RWS + o0
    const int o0     = 2*tid;
    const int m_out  = o0 >> 5;
    const int c_out  = o0 & 31;
    const int brow_o = r*TM + m_out;
    const int hcol_o = q*TN + c_out;
    float2 bias;
    bias.x = bih[layer*HH + hcol_o]   + bhh[layer*HH + hcol_o];
    bias.y = bih[layer*HH + hcol_o+1] + bhh[layer*HH + hcol_o+1];

    __syncthreads();

    const float* AbR = As + (size_t)(8*rg)*AS_STRIDE;

    for (int t = 0; t < TT; ++t) {
        // ============ per-warp-group: wait + stage own columns ============
        if (!on_path) {
            if (layer == 0) {
                #pragma unroll
                for (int i = 0; i < 8; ++i) {
                    int mm = mr_st + 2*i;
                    const float4* xp = (const float4*)(x + ((size_t)(r*TM+mm)*TT + t)*IDIM);
                    stage_f4(As, mm, kk0, __ldg(xp + s0));
                    stage_f4(As, mm, kk1, __ldg(xp + s1));
                }
            } else {
                if (lane == 0) spin_ge(&g_done1[t*NBAND + r], NQ);
                __syncwarp();
                const float* hb = &g_h1[t&(RING-1)][r*TM][0];
                #pragma unroll
                for (int i = 0; i < 8; ++i) {
                    int mm = mr_st + 2*i;
                    const float* hp = hb + (size_t)mm*HH;
                    stage_f4(As, mm, kk0, ldcg4(hp + s0*4));
                    stage_f4(As, mm, kk1, ldcg4(hp + s1*4));
                }
            }
        } else {
            if (layer == 0) {
                if (lane == 0) {
                    if (t > 0)     spin_ge(&g_done1[(t-1)*NBAND + r], NQ);
                    if (t >= RING) spin_ge(&g_done2[(t-RING)*NBAND + r], NQ);
                }
                __syncwarp();
                #pragma unroll
                for (int i = 0; i < 8; ++i) {
                    int mm = mr_st + 2*i;
                    int b  = r*TM + mm;
                    const float* hp = (t == 0) ? (h0 + (size_t)b*HH)
                                               : &g_h1[(t-1)&(RING-1)][b][0];
                    stage_f4(As, mm, kk0, ldcg4(hp + s0*4));
                    stage_f4(As, mm, kk1, ldcg4(hp + s1*4));
                }
            } else {
                if (lane == 0 && t > 0) spin_ge(&g_done2[(t-1)*NBAND + r], NQ);
                __syncwarp();
                #pragma unroll
                for (int i = 0; i < 8; ++i) {
                    int mm = mr_st + 2*i;
                    int b  = r*TM + mm;
                    const float* hp = (t == 0) ? (h0 + (size_t)BB*HH + (size_t)b*HH)
                                               : (out + ((size_t)b*TT + (t-1))*HH);
                    stage_f4(As, mm, kk0, ldcg4(hp + s0*4));
                    stage_f4(As, mm, kk1, ldcg4(hp + s1*4));
                }
            }
        }
        __syncwarp();   // warp reads only its own staged columns

        // ---- GEMM: 8 rows x 8 cols per lane, N-packed FMA2, interleaved k-subslice ----
        unsigned long long acc[32];   // acc[j*4+p] = {out(8rg+j, c0+2p), out(.., c0+2p+1)}
        #pragma unroll
        for (int i2 = 0; i2 < 32; ++i2) acc[i2] = 0ull;

        int kf = kf0;
        #pragma unroll 4
        for (int i = 0; i < 16; ++i, kf += 8) {
            int ka = kf ^ xrA;
            int kb = kf ^ xrB;
            const float* Wk = Wn + (size_t)kf*32 + c0;
            ulonglong2 W0a = *(const ulonglong2*)(Wk);        // k:   col pairs p0,p1
            ulonglong2 W0b = *(const ulonglong2*)(Wk + 4);    // k:   col pairs p2,p3
            ulonglong2 W1a = *(const ulonglong2*)(Wk + 32);   // k+1: col pairs p0,p1
            ulonglong2 W1b = *(const ulonglong2*)(Wk + 36);   // k+1: col pairs p2,p3
            #pragma unroll
            for (int jj = 0; jj < 8; ++jj) {
                int kx = (jj < 4) ? ka : kb;
                unsigned long long a01 =
                    *(const unsigned long long*)(AbR + (size_t)jj*AS_STRIDE + kx);
                float lo, hi;
                asm("mov.b64 {%0, %1}, %2;" : "=f"(lo), "=f"(hi) : "l"(a01));
                unsigned long long aL, aH;
                asm("mov.b64 %0, {%1, %1};" : "=l"(aL) : "f"(lo));
                asm("mov.b64 %0, {%1, %1};" : "=l"(aH) : "f"(hi));
                fma2(acc[jj*4+0], aL, W0a.x);
                fma2(acc[jj*4+1], aL, W0a.y);
                fma2(acc[jj*4+2], aL, W0b.x);
                fma2(acc[jj*4+3], aL, W0b.y);
                fma2(acc[jj*4+0], aH, W1a.x);
                fma2(acc[jj*4+1], aH, W1a.y);
                fma2(acc[jj*4+2], aH, W1b.x);
                fma2(acc[jj*4+3], aH, W1b.y);
            }
        }

        // ---- fold ks-pairs via shfl, store partials (slices s = 2w + ks/2) ----
        {
            float s[64];
            #pragma unroll
            for (int t2 = 0; t2 < 32; ++t2) {
                asm("mov.b64 {%0, %1}, %2;"
                    : "=f"(s[2*t2]), "=f"(s[2*t2+1]) : "l"(acc[t2]));
            }
            #pragma unroll
            for (int v = 0; v < 64; ++v)
                s[v] += __shfl_xor_sync(0xffffffffu, s[v], 8);

            if ((ks & 1) == 0) {
                float* Rw = Red + (2*w + (ks >> 1))*RWS + (8*rg)*RMS + c0;
                #pragma unroll
                for (int jj = 0; jj < 8; ++jj) {
                    *(float4*)(Rw + jj*RMS)
                        = make_float4(s[jj*8+0], s[jj*8+1], s[jj*8+2], s[jj*8+3]);
                    *(float4*)(Rw + jj*RMS + 4)
                        = make_float4(s[jj*8+4], s[jj*8+5], s[jj*8+6], s[jj*8+7]);
                }
            }
        }
        __syncthreads();   // join warp groups: partials -> reduce

        // ---- cross-slice reduce (16 slices), bias, tanh, store ----
        float2 acc2 = make_float2(0.f, 0.f);
        const float* Rb = Red + o0;   // slice*RWS + m_out*RMS + c_out = slice*RWS + o0
        #pragma unroll
        for (int ss2 = 0; ss2 < NSLICE; ++ss2) {
            float2 v = *(const float2*)(Rb + ss2*RWS);
            acc2.x += v.x; acc2.y += v.y;
        }
        float2 res;
        res.x = fast_tanh(acc2.x + bias.x);
        res.y = fast_tanh(acc2.y + bias.y);

        if (layer == 0) {
            *(float2*)&g_h1[t&(RING-1)][brow_o][hcol_o] = res;
            if (t == TT-1)
                *(float2*)(out + (size_t)BB*TT*HH + (size_t)brow_o*HH + hcol_o) = res;
        } else {
            *(float2*)(out + ((size_t)brow_o*TT + t)*HH + hcol_o) = res;
            if (t == TT-1)
                *(float2*)(out + (size_t)BB*TT*HH + (size_t)BB*HH
                               + (size_t)brow_o*HH + hcol_o) = res;
        }

        __syncthreads();   // all stores done before release
        if (tid == 0) {
            int* ctr = (layer == 0) ? &g_done1[t*NBAND + r] : &g_done2[t*NBAND + r];
            red_release(ctr);
        }
    }
}

extern "C" void kernel_launch(void* const* d_in, const int* in_sizes, int n_in,
                              void* d_out, int out_size)
{
    const float* x   = (const float*)d_in[0];
    const float* h0  = (const float*)d_in[1];
    const float* Wih = (const float*)d_in[2];
    const float* bih = (const float*)d_in[3];
    const float* Whh = (const float*)d_in[4];
    const float* bhh = (const float*)d_in[5];
    float* out = (float*)d_out;

    const size_t smem_bytes = (size_t)SMEM_FLOATS * sizeof(float); // ~229.6 KB
    cudaFuncSetAttribute(rnn_persistent,
                         cudaFuncAttributeMaxDynamicSharedMemorySize,
                         (int)smem_bytes);

    rnn_init_counters<<<(TT*NBAND + 255)/256, 256>>>();
    rnn_persistent<<<NCTA, NTHR, smem_bytes>>>(x, h0, Wih, bih, Whh, bhh, out);
}